// round 1
// baseline (speedup 1.0000x reference)
#include <cuda_runtime.h>

// CausalAttention: out = softmax_causal((xWq)(xWk)^T / sqrt(d)) (xWv)
// B=4, N=2048, D=1024, fp32 throughout.
//
// Round-0 baseline: classic 128x128x8 SIMT fp32 SGEMM for all three GEMM
// stages + shared-memory row softmax. Causality exploited:
//   - QK^T: skip tiles strictly above the diagonal (halves GEMM2)
//   - softmax: zero-pads each P row to the next 128 boundary
//   - PV: K-loop bounded at m0+BM (halves GEMM3)

#define BATCH 4
#define SEQ   2048
#define DIM   1024

#define BM 128
#define BN 128
#define BK 8

// Scratch (device globals are the sanctioned no-alloc workaround).
__device__ float g_Q[BATCH * SEQ * DIM];              // 32 MB
__device__ float g_K[BATCH * SEQ * DIM];              // 32 MB
__device__ float g_V[BATCH * SEQ * DIM];              // 32 MB
__device__ float g_S[BATCH * SEQ * SEQ];              // 64 MB

// C[M,N] = A[M,K] * B[N,K]^T   (both operands K-contiguous / "NT")
// Batched via blockIdx.z with explicit batch strides. causal!=0 skips tiles
// strictly above the diagonal (n0 > m0).
__global__ void __launch_bounds__(256, 2) gemm_nt(
    const float* __restrict__ A, const float* __restrict__ Bw,
    float* __restrict__ C,
    int M, int N, int K,
    long long sA, long long sB, long long sC, int causal)
{
    const int m0 = blockIdx.y * BM;
    const int n0 = blockIdx.x * BN;
    if (causal && n0 > m0) return;

    const float* Ab = A  + (long long)blockIdx.z * sA;
    const float* Bb = Bw + (long long)blockIdx.z * sB;
    float*       Cb = C  + (long long)blockIdx.z * sC;

    __shared__ float As[BK][BM];
    __shared__ float Bs[BK][BN];

    const int tid = threadIdx.x;
    const int tr  = tid >> 4;        // 0..15 (row of 8x8 micro-tile)
    const int tc  = tid & 15;        // 0..15 (col of 8x8 micro-tile)
    const int lr  = tid >> 1;        // 0..127 load row
    const int lk  = (tid & 1) * 4;   // 0 or 4 load k-offset

    float acc[8][8];
#pragma unroll
    for (int i = 0; i < 8; i++)
#pragma unroll
        for (int j = 0; j < 8; j++) acc[i][j] = 0.f;

    const float* Aptr = Ab + (long long)(m0 + lr) * K + lk;
    const float* Bptr = Bb + (long long)(n0 + lr) * K + lk;

    for (int k0 = 0; k0 < K; k0 += BK) {
        float4 av = *(const float4*)(Aptr + k0);
        float4 bv = *(const float4*)(Bptr + k0);
        As[lk + 0][lr] = av.x; As[lk + 1][lr] = av.y;
        As[lk + 2][lr] = av.z; As[lk + 3][lr] = av.w;
        Bs[lk + 0][lr] = bv.x; Bs[lk + 1][lr] = bv.y;
        Bs[lk + 2][lr] = bv.z; Bs[lk + 3][lr] = bv.w;
        __syncthreads();
#pragma unroll
        for (int kk = 0; kk < BK; kk++) {
            float a[8], b[8];
#pragma unroll
            for (int i = 0; i < 8; i++) a[i] = As[kk][tr * 8 + i];
#pragma unroll
            for (int j = 0; j < 8; j++) b[j] = Bs[kk][tc * 8 + j];
#pragma unroll
            for (int i = 0; i < 8; i++)
#pragma unroll
                for (int j = 0; j < 8; j++)
                    acc[i][j] = fmaf(a[i], b[j], acc[i][j]);
        }
        __syncthreads();
    }

#pragma unroll
    for (int i = 0; i < 8; i++) {
        long long roff = (long long)(m0 + tr * 8 + i) * N + n0 + tc * 8;
        *(float4*)(Cb + roff)     = make_float4(acc[i][0], acc[i][1], acc[i][2], acc[i][3]);
        *(float4*)(Cb + roff + 4) = make_float4(acc[i][4], acc[i][5], acc[i][6], acc[i][7]);
    }
}

// O[SEQ,DIM] = P[SEQ,SEQ] * V[SEQ,DIM]  ("NN"), per batch via blockIdx.z.
// Causal: row tile [m0, m0+BM) only needs k < m0+BM (softmax zero-padded
// P up to the tile boundary, so no per-row masking is needed).
__global__ void __launch_bounds__(256, 2) gemm_nn_pv(
    const float* __restrict__ P, const float* __restrict__ V,
    float* __restrict__ O)
{
    const int m0 = blockIdx.y * BM;
    const int n0 = blockIdx.x * BN;
    const int z  = blockIdx.z;

    const float* Pb = P + (long long)z * SEQ * SEQ;
    const float* Vb = V + (long long)z * SEQ * DIM;
    float*       Ob = O + (long long)z * SEQ * DIM;

    const int kend = m0 + BM;   // <= SEQ always

    __shared__ float As[BK][BM];
    __shared__ float Bs[BK][BN];

    const int tid = threadIdx.x;
    const int tr  = tid >> 4;
    const int tc  = tid & 15;
    const int lr  = tid >> 1;
    const int lk  = (tid & 1) * 4;
    const int br  = tid >> 5;          // 0..7  (V row within k-slab)
    const int bc  = (tid & 31) * 4;    // 0..124 (V col, float4)

    float acc[8][8];
#pragma unroll
    for (int i = 0; i < 8; i++)
#pragma unroll
        for (int j = 0; j < 8; j++) acc[i][j] = 0.f;

    const float* Aptr = Pb + (long long)(m0 + lr) * SEQ + lk;

    for (int k0 = 0; k0 < kend; k0 += BK) {
        float4 av = *(const float4*)(Aptr + k0);
        float4 bv = *(const float4*)(Vb + (long long)(k0 + br) * DIM + n0 + bc);
        As[lk + 0][lr] = av.x; As[lk + 1][lr] = av.y;
        As[lk + 2][lr] = av.z; As[lk + 3][lr] = av.w;
        *(float4*)&Bs[br][bc] = bv;
        __syncthreads();
#pragma unroll
        for (int kk = 0; kk < BK; kk++) {
            float a[8], b[8];
#pragma unroll
            for (int i = 0; i < 8; i++) a[i] = As[kk][tr * 8 + i];
#pragma unroll
            for (int j = 0; j < 8; j++) b[j] = Bs[kk][tc * 8 + j];
#pragma unroll
            for (int i = 0; i < 8; i++)
#pragma unroll
                for (int j = 0; j < 8; j++)
                    acc[i][j] = fmaf(a[i], b[j], acc[i][j]);
        }
        __syncthreads();
    }

#pragma unroll
    for (int i = 0; i < 8; i++) {
        long long roff = (long long)(m0 + tr * 8 + i) * DIM + n0 + tc * 8;
        *(float4*)(Ob + roff)     = make_float4(acc[i][0], acc[i][1], acc[i][2], acc[i][3]);
        *(float4*)(Ob + roff + 4) = make_float4(acc[i][4], acc[i][5], acc[i][6], acc[i][7]);
    }
}

// One block per (batch,row). softmax(s * 1/sqrt(1024)) over columns [0, q],
// writes normalized probs in place and ZEROS columns (q, next_128_boundary)
// so the PV kernel can use tile-granular K bounds.
__global__ void __launch_bounds__(256) softmax_causal(float* __restrict__ S)
{
    const int row = blockIdx.x;            // b*SEQ + q (S is row-contiguous)
    const int q   = row & (SEQ - 1);
    float* Sr = S + (long long)row * SEQ;

    __shared__ float buf[SEQ];
    __shared__ float red[256];
    const int tid = threadIdx.x;
    const int L   = q + 1;
    const float scale = 0.03125f;          // 1/sqrt(1024)

    float m = -3.402823466e38f;
    for (int j = tid; j < L; j += 256) {
        float v = Sr[j];
        buf[j] = v;
        m = fmaxf(m, v);
    }
    red[tid] = m; __syncthreads();
    for (int s = 128; s; s >>= 1) {
        if (tid < s) red[tid] = fmaxf(red[tid], red[tid + s]);
        __syncthreads();
    }
    const float mv = red[0];
    __syncthreads();

    float sum = 0.f;
    for (int j = tid; j < L; j += 256) {
        float e = __expf((buf[j] - mv) * scale);
        buf[j] = e;
        sum += e;
    }
    red[tid] = sum; __syncthreads();
    for (int s = 128; s; s >>= 1) {
        if (tid < s) red[tid] += red[tid + s];
        __syncthreads();
    }
    const float inv = 1.0f / red[0];

    const int pend = ((q >> 7) + 1) << 7;  // pad to next 128 boundary
    for (int j = tid; j < pend; j += 256)
        Sr[j] = (j < L) ? buf[j] * inv : 0.f;
}

extern "C" void kernel_launch(void* const* d_in, const int* in_sizes, int n_in,
                              void* d_out, int out_size)
{
    const float* x  = (const float*)d_in[0];
    const float* Wq = (const float*)d_in[1];
    const float* Wk = (const float*)d_in[2];
    const float* Wv = (const float*)d_in[3];
    float* out = (float*)d_out;

    float *Q, *K, *V, *S;
    cudaGetSymbolAddress((void**)&Q, g_Q);
    cudaGetSymbolAddress((void**)&K, g_K);
    cudaGetSymbolAddress((void**)&V, g_V);
    cudaGetSymbolAddress((void**)&S, g_S);

    dim3 blk(256);

    // Stage 1: Q/K/V projections: [8192,1024] = x * W^T
    dim3 g1(DIM / BN, (BATCH * SEQ) / BM, 1);
    gemm_nt<<<g1, blk>>>(x, Wq, Q, BATCH * SEQ, DIM, DIM, 0, 0, 0, 0);
    gemm_nt<<<g1, blk>>>(x, Wk, K, BATCH * SEQ, DIM, DIM, 0, 0, 0, 0);
    gemm_nt<<<g1, blk>>>(x, Wv, V, BATCH * SEQ, DIM, DIM, 0, 0, 0, 0);

    // Stage 2: S = Q * K^T per batch, lower-triangular tiles only
    dim3 g2(SEQ / BN, SEQ / BM, BATCH);
    gemm_nt<<<g2, blk>>>(Q, K, S, SEQ, SEQ, DIM,
                         (long long)SEQ * DIM, (long long)SEQ * DIM,
                         (long long)SEQ * SEQ, 1);

    // Stage 3: causal softmax (in place, zero-pads to tile boundary)
    softmax_causal<<<BATCH * SEQ, 256>>>(S);

    // Stage 4: O = P * V per batch, K bounded by causal tile limit
    dim3 g3(DIM / BN, SEQ / BM, BATCH);
    gemm_nn_pv<<<g3, blk>>>(S, V, out);
}

// round 2
// speedup vs baseline: 3.8455x; 3.8455x over previous
#include <cuda_runtime.h>
#include <cstdint>

// CausalAttention via tf32 mma.sync tensor cores.
// B=4, N=2048, D=1024, fp32 in/out; tf32 (RNA-rounded) mma for all GEMMs.

#define BATCH 4
#define SEQ   2048
#define DIM   1024

#define PADA 36              // 128x32 tiles stored [r][36] (conflict-free frags)
#define PADV 136             // 32x128 V tiles stored [k][136]
#define ATILE (128 * PADA)   // floats per A/B buffer (4608)
#define VTILE (32 * PADV)    // floats per V buffer (4352)

__device__ float g_Q[BATCH * SEQ * DIM];
__device__ float g_K[BATCH * SEQ * DIM];
__device__ float g_V[BATCH * SEQ * DIM];
__device__ float g_S[BATCH * SEQ * SEQ];

__device__ __forceinline__ uint32_t f2tf32(float f) {
    uint32_t u;
    asm("cvt.rna.tf32.f32 %0, %1;" : "=r"(u) : "f"(f));
    return u;
}

__device__ __forceinline__ void cpasync16(uint32_t dst, const void* src) {
    asm volatile("cp.async.cg.shared.global [%0], [%1], 16;" :: "r"(dst), "l"(src));
}

__device__ __forceinline__ void mma_tf32(float c[4], const uint32_t a[4], const uint32_t b[2]) {
    asm volatile(
        "mma.sync.aligned.m16n8k8.row.col.f32.tf32.tf32.f32 "
        "{%0,%1,%2,%3}, {%4,%5,%6,%7}, {%8,%9}, {%0,%1,%2,%3};"
        : "+f"(c[0]), "+f"(c[1]), "+f"(c[2]), "+f"(c[3])
        : "r"(a[0]), "r"(a[1]), "r"(a[2]), "r"(a[3]), "r"(b[0]), "r"(b[1]));
}

// C[M,N] = A[M,K] * B[N,K]^T  (NT, K-contiguous operands), batched by blockIdx.z.
// causal!=0 skips tiles strictly above the diagonal.
__global__ __launch_bounds__(256, 2) void gemm_nt_tc(
    const float* __restrict__ A, const float* __restrict__ Bw,
    float* __restrict__ C, int M, int N, int K,
    long long sA, long long sB, long long sC, int causal)
{
    const int m0 = blockIdx.y * 128;
    const int n0 = blockIdx.x * 128;
    if (causal && n0 > m0) return;

    const float* Ab = A  + (long long)blockIdx.z * sA + (long long)m0 * K;
    const float* Bb = Bw + (long long)blockIdx.z * sB + (long long)n0 * K;
    float*       Cb = C  + (long long)blockIdx.z * sC;

    extern __shared__ float sm[];
    float* Asm = sm;               // [2][ATILE]
    float* Bsm = sm + 2 * ATILE;   // [2][ATILE]
    const uint32_t aB = (uint32_t)__cvta_generic_to_shared(Asm);
    const uint32_t bB = (uint32_t)__cvta_generic_to_shared(Bsm);

    const int tid  = threadIdx.x;
    const int lane = tid & 31, warp = tid >> 5;
    const int wm = warp >> 1, wn = warp & 1;
    const int gid = lane >> 2, tg = lane & 3;

    float c[2][8][4];
#pragma unroll
    for (int i = 0; i < 2; i++)
#pragma unroll
        for (int j = 0; j < 8; j++)
#pragma unroll
            for (int e = 0; e < 4; e++) c[i][j][e] = 0.f;

    const int nt = K >> 5;

    auto load_tiles = [&](int t, int buf) {
        const float* Ag = Ab + t * 32;
        const float* Bg = Bb + t * 32;
#pragma unroll
        for (int i = 0; i < 4; i++) {
            int idx = tid + i * 256;
            int row = idx >> 3, kc = (idx & 7) << 2;
            uint32_t so = (uint32_t)(buf * ATILE + row * PADA + kc) * 4u;
            cpasync16(aB + so, Ag + (long long)row * K + kc);
            cpasync16(bB + so, Bg + (long long)row * K + kc);
        }
        asm volatile("cp.async.commit_group;");
    };

    auto compute = [&](int buf) {
        const float* At = Asm + buf * ATILE;
        const float* Bt = Bsm + buf * ATILE;
#pragma unroll
        for (int ks = 0; ks < 4; ks++) {
            const int k0 = ks * 8;
            uint32_t a[2][4];
#pragma unroll
            for (int i = 0; i < 2; i++) {
                int m = wm * 32 + i * 16 + gid;
                a[i][0] = f2tf32(At[m * PADA + k0 + tg]);
                a[i][1] = f2tf32(At[(m + 8) * PADA + k0 + tg]);
                a[i][2] = f2tf32(At[m * PADA + k0 + tg + 4]);
                a[i][3] = f2tf32(At[(m + 8) * PADA + k0 + tg + 4]);
            }
            uint32_t b[8][2];
#pragma unroll
            for (int j = 0; j < 8; j++) {
                int n = wn * 64 + j * 8 + gid;
                b[j][0] = f2tf32(Bt[n * PADA + k0 + tg]);
                b[j][1] = f2tf32(Bt[n * PADA + k0 + tg + 4]);
            }
#pragma unroll
            for (int i = 0; i < 2; i++)
#pragma unroll
                for (int j = 0; j < 8; j++) mma_tf32(c[i][j], a[i], b[j]);
        }
    };

    load_tiles(0, 0);
    for (int t = 0; t < nt; t++) {
        if (t + 1 < nt) {
            load_tiles(t + 1, (t + 1) & 1);
            asm volatile("cp.async.wait_group 1;");
        } else {
            asm volatile("cp.async.wait_group 0;");
        }
        __syncthreads();
        compute(t & 1);
        __syncthreads();
    }

#pragma unroll
    for (int i = 0; i < 2; i++) {
        int mr = m0 + wm * 32 + i * 16 + gid;
#pragma unroll
        for (int j = 0; j < 8; j++) {
            int col = n0 + wn * 64 + j * 8 + 2 * tg;
            *(float2*)(Cb + (long long)mr * N + col)       = make_float2(c[i][j][0], c[i][j][1]);
            *(float2*)(Cb + (long long)(mr + 8) * N + col) = make_float2(c[i][j][2], c[i][j][3]);
        }
    }
}

// O[SEQ,DIM] = P[SEQ,SEQ] * V[SEQ,DIM] (NN), batched; causal K-bound at m0+128.
__global__ __launch_bounds__(256, 2) void gemm_pv_tc(
    const float* __restrict__ P, const float* __restrict__ V, float* __restrict__ O)
{
    const int m0 = blockIdx.y * 128;
    const int n0 = blockIdx.x * 128;
    const int z  = blockIdx.z;

    const float* Pb = P + (long long)z * SEQ * SEQ + (long long)m0 * SEQ;
    const float* Vb = V + (long long)z * SEQ * DIM;
    float*       Ob = O + (long long)z * SEQ * DIM;

    extern __shared__ float sm[];
    float* Psm = sm;               // [2][ATILE]
    float* Vsm = sm + 2 * ATILE;   // [2][VTILE]
    const uint32_t pB = (uint32_t)__cvta_generic_to_shared(Psm);
    const uint32_t vB = (uint32_t)__cvta_generic_to_shared(Vsm);

    const int tid  = threadIdx.x;
    const int lane = tid & 31, warp = tid >> 5;
    const int wm = warp >> 1, wn = warp & 1;
    const int gid = lane >> 2, tg = lane & 3;

    float c[2][8][4];
#pragma unroll
    for (int i = 0; i < 2; i++)
#pragma unroll
        for (int j = 0; j < 8; j++)
#pragma unroll
            for (int e = 0; e < 4; e++) c[i][j][e] = 0.f;

    const int nt = (m0 + 128) >> 5;   // causal bound

    auto load_tiles = [&](int t, int buf) {
        const float* Pg = Pb + t * 32;
        const float* Vg = Vb + (long long)(t * 32) * DIM + n0;
#pragma unroll
        for (int i = 0; i < 4; i++) {
            int idx = tid + i * 256;
            int prow = idx >> 3, pkc = (idx & 7) << 2;
            cpasync16(pB + (uint32_t)(buf * ATILE + prow * PADA + pkc) * 4u,
                      Pg + (long long)prow * SEQ + pkc);
            int vrow = idx >> 5, vc = (idx & 31) << 2;
            cpasync16(vB + (uint32_t)(buf * VTILE + vrow * PADV + vc) * 4u,
                      Vg + (long long)vrow * DIM + vc);
        }
        asm volatile("cp.async.commit_group;");
    };

    auto compute = [&](int buf) {
        const float* Pt = Psm + buf * ATILE;
        const float* Vt = Vsm + buf * VTILE;
#pragma unroll
        for (int ks = 0; ks < 4; ks++) {
            const int k0 = ks * 8;
            uint32_t a[2][4];
#pragma unroll
            for (int i = 0; i < 2; i++) {
                int m = wm * 32 + i * 16 + gid;
                a[i][0] = f2tf32(Pt[m * PADA + k0 + tg]);
                a[i][1] = f2tf32(Pt[(m + 8) * PADA + k0 + tg]);
                a[i][2] = f2tf32(Pt[m * PADA + k0 + tg + 4]);
                a[i][3] = f2tf32(Pt[(m + 8) * PADA + k0 + tg + 4]);
            }
            uint32_t b[8][2];
#pragma unroll
            for (int j = 0; j < 8; j++) {
                int n = wn * 64 + j * 8 + gid;
                b[j][0] = f2tf32(Vt[(k0 + tg) * PADV + n]);
                b[j][1] = f2tf32(Vt[(k0 + tg + 4) * PADV + n]);
            }
#pragma unroll
            for (int i = 0; i < 2; i++)
#pragma unroll
                for (int j = 0; j < 8; j++) mma_tf32(c[i][j], a[i], b[j]);
        }
    };

    load_tiles(0, 0);
    for (int t = 0; t < nt; t++) {
        if (t + 1 < nt) {
            load_tiles(t + 1, (t + 1) & 1);
            asm volatile("cp.async.wait_group 1;");
        } else {
            asm volatile("cp.async.wait_group 0;");
        }
        __syncthreads();
        compute(t & 1);
        __syncthreads();
    }

#pragma unroll
    for (int i = 0; i < 2; i++) {
        int mr = m0 + wm * 32 + i * 16 + gid;
#pragma unroll
        for (int j = 0; j < 8; j++) {
            int col = n0 + wn * 64 + j * 8 + 2 * tg;
            *(float2*)(Ob + (long long)mr * DIM + col)       = make_float2(c[i][j][0], c[i][j][1]);
            *(float2*)(Ob + (long long)(mr + 8) * DIM + col) = make_float2(c[i][j][2], c[i][j][3]);
        }
    }
}

// Causal softmax: one block per (b, q) row; normalize cols [0,q], zero-pad
// up to the next 128 boundary so PV can use tile-granular K bounds.
__global__ __launch_bounds__(256) void softmax_causal(float* __restrict__ S)
{
    const int row = blockIdx.x;
    const int q   = row & (SEQ - 1);
    float* Sr = S + (long long)row * SEQ;

    __shared__ float buf[SEQ];
    __shared__ float red[256];
    const int tid = threadIdx.x;
    const int L   = q + 1;
    const float scale = 0.03125f;   // 1/sqrt(1024)

    float m = -3.402823466e38f;
    for (int j = tid; j < L; j += 256) {
        float v = Sr[j];
        buf[j] = v;
        m = fmaxf(m, v);
    }
    red[tid] = m; __syncthreads();
    for (int s = 128; s; s >>= 1) {
        if (tid < s) red[tid] = fmaxf(red[tid], red[tid + s]);
        __syncthreads();
    }
    const float mv = red[0];
    __syncthreads();

    float sum = 0.f;
    for (int j = tid; j < L; j += 256) {
        float e = __expf((buf[j] - mv) * scale);
        buf[j] = e;
        sum += e;
    }
    red[tid] = sum; __syncthreads();
    for (int s = 128; s; s >>= 1) {
        if (tid < s) red[tid] += red[tid + s];
        __syncthreads();
    }
    const float inv = 1.0f / red[0];

    const int pend = ((q >> 7) + 1) << 7;
    for (int j = tid; j < pend; j += 256)
        Sr[j] = (j < L) ? buf[j] * inv : 0.f;
}

extern "C" void kernel_launch(void* const* d_in, const int* in_sizes, int n_in,
                              void* d_out, int out_size)
{
    const float* x  = (const float*)d_in[0];
    const float* Wq = (const float*)d_in[1];
    const float* Wk = (const float*)d_in[2];
    const float* Wv = (const float*)d_in[3];
    float* out = (float*)d_out;

    float *Q, *K, *V, *S;
    cudaGetSymbolAddress((void**)&Q, g_Q);
    cudaGetSymbolAddress((void**)&K, g_K);
    cudaGetSymbolAddress((void**)&V, g_V);
    cudaGetSymbolAddress((void**)&S, g_S);

    const int smemNT = 4 * ATILE * 4;                 // 73728 B
    const int smemPV = (2 * ATILE + 2 * VTILE) * 4;   // 71680 B
    cudaFuncSetAttribute(gemm_nt_tc, cudaFuncAttributeMaxDynamicSharedMemorySize, smemNT);
    cudaFuncSetAttribute(gemm_pv_tc, cudaFuncAttributeMaxDynamicSharedMemorySize, smemPV);

    dim3 blk(256);

    dim3 g1(DIM / 128, (BATCH * SEQ) / 128, 1);
    gemm_nt_tc<<<g1, blk, smemNT>>>(x, Wq, Q, BATCH * SEQ, DIM, DIM, 0, 0, 0, 0);
    gemm_nt_tc<<<g1, blk, smemNT>>>(x, Wk, K, BATCH * SEQ, DIM, DIM, 0, 0, 0, 0);
    gemm_nt_tc<<<g1, blk, smemNT>>>(x, Wv, V, BATCH * SEQ, DIM, DIM, 0, 0, 0, 0);

    dim3 g2(SEQ / 128, SEQ / 128, BATCH);
    gemm_nt_tc<<<g2, blk, smemNT>>>(Q, K, S, SEQ, SEQ, DIM,
                                    (long long)SEQ * DIM, (long long)SEQ * DIM,
                                    (long long)SEQ * SEQ, 1);

    softmax_causal<<<BATCH * SEQ, 256>>>(S);

    dim3 g3(DIM / 128, SEQ / 128, BATCH);
    gemm_pv_tc<<<g3, blk, smemPV>>>(S, V, out);
}

// round 5
// speedup vs baseline: 3.9876x; 1.0369x over previous
#include <cuda_runtime.h>
#include <cstdint>

// CausalAttention via tf32 mma.sync tensor cores.
// B=4, N=2048, D=1024, fp32 in/out.
// R3 (3rd submit; two infra timeouts): all tf32 RNA rounding hoisted OUT of
// GEMM mainloops — inputs pre-rounded (x, W in a pre-pass; Q/K/V in projection
// epilogue; P in softmax epilogue), inner loops load raw bits. Numerically
// identical to R2, fewer issue slots.

#define BATCH 4
#define SEQ   2048
#define DIM   1024

#define PADA 36              // 128x32 tiles stored [r][36] (conflict-free frags)
#define PADV 136             // 32x128 V tiles stored [k][136]
#define ATILE (128 * PADA)
#define VTILE (32 * PADV)

__device__ float g_X [BATCH * SEQ * DIM];
__device__ float g_Wq[DIM * DIM];
__device__ float g_Wk[DIM * DIM];
__device__ float g_Wv[DIM * DIM];
__device__ float g_Q [BATCH * SEQ * DIM];
__device__ float g_K [BATCH * SEQ * DIM];
__device__ float g_V [BATCH * SEQ * DIM];
__device__ float g_S [BATCH * SEQ * SEQ];

__device__ __forceinline__ uint32_t f2tf32(float f) {
    uint32_t u;
    asm("cvt.rna.tf32.f32 %0, %1;" : "=r"(u) : "f"(f));
    return u;
}
__device__ __forceinline__ float rnd_tf32(float f) {
    return __uint_as_float(f2tf32(f));
}

__device__ __forceinline__ void cpasync16(uint32_t dst, const void* src) {
    asm volatile("cp.async.cg.shared.global [%0], [%1], 16;" :: "r"(dst), "l"(src));
}

__device__ __forceinline__ void mma_tf32(float c[4], const uint32_t a[4], const uint32_t b[2]) {
    asm volatile(
        "mma.sync.aligned.m16n8k8.row.col.f32.tf32.tf32.f32 "
        "{%0,%1,%2,%3}, {%4,%5,%6,%7}, {%8,%9}, {%0,%1,%2,%3};"
        : "+f"(c[0]), "+f"(c[1]), "+f"(c[2]), "+f"(c[3])
        : "r"(a[0]), "r"(a[1]), "r"(a[2]), "r"(a[3]), "r"(b[0]), "r"(b[1]));
}

// Elementwise RNA-round to tf32 (stored as fp32). n divisible by 4.
__global__ void round_tf32_kernel(const float* __restrict__ src,
                                  float* __restrict__ dst, int n4)
{
    int i = blockIdx.x * blockDim.x + threadIdx.x;
    if (i < n4) {
        float4 v = ((const float4*)src)[i];
        v.x = rnd_tf32(v.x); v.y = rnd_tf32(v.y);
        v.z = rnd_tf32(v.z); v.w = rnd_tf32(v.w);
        ((float4*)dst)[i] = v;
    }
}

// Fused QKV projection: C_z[M,N] = X[M,K] * W_z[N,K]^T for z = 0,1,2.
// Output rounded to tf32.
__global__ __launch_bounds__(256, 2) void gemm_qkv_tc(
    const float* __restrict__ X,
    const float* __restrict__ Wq, const float* __restrict__ Wk,
    const float* __restrict__ Wv,
    float* __restrict__ Q, float* __restrict__ K, float* __restrict__ V)
{
    const int m0 = blockIdx.y * 128;
    const int n0 = blockIdx.x * 128;
    const float* Bw = (blockIdx.z == 0) ? Wq : (blockIdx.z == 1) ? Wk : Wv;
    float*       C  = (blockIdx.z == 0) ? Q  : (blockIdx.z == 1) ? K  : V;

    const float* Ab = X  + (long long)m0 * DIM;
    const float* Bb = Bw + (long long)n0 * DIM;

    extern __shared__ float sm[];
    float* Asm = sm;
    float* Bsm = sm + 2 * ATILE;
    const uint32_t aB = (uint32_t)__cvta_generic_to_shared(Asm);
    const uint32_t bB = (uint32_t)__cvta_generic_to_shared(Bsm);

    const int tid  = threadIdx.x;
    const int lane = tid & 31, warp = tid >> 5;
    const int wm = warp >> 1, wn = warp & 1;
    const int gid = lane >> 2, tg = lane & 3;

    float c[2][8][4];
#pragma unroll
    for (int i = 0; i < 2; i++)
#pragma unroll
        for (int j = 0; j < 8; j++)
#pragma unroll
            for (int e = 0; e < 4; e++) c[i][j][e] = 0.f;

    const int nt = DIM >> 5;

    auto load_tiles = [&](int t, int buf) {
        const float* Ag = Ab + t * 32;
        const float* Bg = Bb + t * 32;
#pragma unroll
        for (int i = 0; i < 4; i++) {
            int idx = tid + i * 256;
            int row = idx >> 3, kc = (idx & 7) << 2;
            uint32_t so = (uint32_t)(buf * ATILE + row * PADA + kc) * 4u;
            cpasync16(aB + so, Ag + (long long)row * DIM + kc);
            cpasync16(bB + so, Bg + (long long)row * DIM + kc);
        }
        asm volatile("cp.async.commit_group;");
    };

    auto compute = [&](int buf) {
        const float* At = Asm + buf * ATILE;
        const float* Bt = Bsm + buf * ATILE;
#pragma unroll
        for (int ks = 0; ks < 4; ks++) {
            const int k0 = ks * 8;
            uint32_t a[2][4];
#pragma unroll
            for (int i = 0; i < 2; i++) {
                int m = wm * 32 + i * 16 + gid;
                a[i][0] = __float_as_uint(At[m * PADA + k0 + tg]);
                a[i][1] = __float_as_uint(At[(m + 8) * PADA + k0 + tg]);
                a[i][2] = __float_as_uint(At[m * PADA + k0 + tg + 4]);
                a[i][3] = __float_as_uint(At[(m + 8) * PADA + k0 + tg + 4]);
            }
            uint32_t b[8][2];
#pragma unroll
            for (int j = 0; j < 8; j++) {
                int n = wn * 64 + j * 8 + gid;
                b[j][0] = __float_as_uint(Bt[n * PADA + k0 + tg]);
                b[j][1] = __float_as_uint(Bt[n * PADA + k0 + tg + 4]);
            }
#pragma unroll
            for (int i = 0; i < 2; i++)
#pragma unroll
                for (int j = 0; j < 8; j++) mma_tf32(c[i][j], a[i], b[j]);
        }
    };

    load_tiles(0, 0);
    for (int t = 0; t < nt; t++) {
        if (t + 1 < nt) {
            load_tiles(t + 1, (t + 1) & 1);
            asm volatile("cp.async.wait_group 1;");
        } else {
            asm volatile("cp.async.wait_group 0;");
        }
        __syncthreads();
        compute(t & 1);
        __syncthreads();
    }

#pragma unroll
    for (int i = 0; i < 2; i++) {
        int mr = m0 + wm * 32 + i * 16 + gid;
#pragma unroll
        for (int j = 0; j < 8; j++) {
            int col = n0 + wn * 64 + j * 8 + 2 * tg;
            *(float2*)(C + (long long)mr * DIM + col) =
                make_float2(rnd_tf32(c[i][j][0]), rnd_tf32(c[i][j][1]));
            *(float2*)(C + (long long)(mr + 8) * DIM + col) =
                make_float2(rnd_tf32(c[i][j][2]), rnd_tf32(c[i][j][3]));
        }
    }
}

// S = Q * K^T per batch (NT), lower-triangular tiles only. Output fp32 (raw).
__global__ __launch_bounds__(256, 2) void gemm_qk_tc(
    const float* __restrict__ Q, const float* __restrict__ K,
    float* __restrict__ S)
{
    const int m0 = blockIdx.y * 128;
    const int n0 = blockIdx.x * 128;
    if (n0 > m0) return;
    const int z = blockIdx.z;

    const float* Ab = Q + (long long)z * SEQ * DIM + (long long)m0 * DIM;
    const float* Bb = K + (long long)z * SEQ * DIM + (long long)n0 * DIM;
    float*       Cb = S + (long long)z * SEQ * SEQ;

    extern __shared__ float sm[];
    float* Asm = sm;
    float* Bsm = sm + 2 * ATILE;
    const uint32_t aB = (uint32_t)__cvta_generic_to_shared(Asm);
    const uint32_t bB = (uint32_t)__cvta_generic_to_shared(Bsm);

    const int tid  = threadIdx.x;
    const int lane = tid & 31, warp = tid >> 5;
    const int wm = warp >> 1, wn = warp & 1;
    const int gid = lane >> 2, tg = lane & 3;

    float c[2][8][4];
#pragma unroll
    for (int i = 0; i < 2; i++)
#pragma unroll
        for (int j = 0; j < 8; j++)
#pragma unroll
            for (int e = 0; e < 4; e++) c[i][j][e] = 0.f;

    const int nt = DIM >> 5;

    auto load_tiles = [&](int t, int buf) {
        const float* Ag = Ab + t * 32;
        const float* Bg = Bb + t * 32;
#pragma unroll
        for (int i = 0; i < 4; i++) {
            int idx = tid + i * 256;
            int row = idx >> 3, kc = (idx & 7) << 2;
            uint32_t so = (uint32_t)(buf * ATILE + row * PADA + kc) * 4u;
            cpasync16(aB + so, Ag + (long long)row * DIM + kc);
            cpasync16(bB + so, Bg + (long long)row * DIM + kc);
        }
        asm volatile("cp.async.commit_group;");
    };

    auto compute = [&](int buf) {
        const float* At = Asm + buf * ATILE;
        const float* Bt = Bsm + buf * ATILE;
#pragma unroll
        for (int ks = 0; ks < 4; ks++) {
            const int k0 = ks * 8;
            uint32_t a[2][4];
#pragma unroll
            for (int i = 0; i < 2; i++) {
                int m = wm * 32 + i * 16 + gid;
                a[i][0] = __float_as_uint(At[m * PADA + k0 + tg]);
                a[i][1] = __float_as_uint(At[(m + 8) * PADA + k0 + tg]);
                a[i][2] = __float_as_uint(At[m * PADA + k0 + tg + 4]);
                a[i][3] = __float_as_uint(At[(m + 8) * PADA + k0 + tg + 4]);
            }
            uint32_t b[8][2];
#pragma unroll
            for (int j = 0; j < 8; j++) {
                int n = wn * 64 + j * 8 + gid;
                b[j][0] = __float_as_uint(Bt[n * PADA + k0 + tg]);
                b[j][1] = __float_as_uint(Bt[n * PADA + k0 + tg + 4]);
            }
#pragma unroll
            for (int i = 0; i < 2; i++)
#pragma unroll
                for (int j = 0; j < 8; j++) mma_tf32(c[i][j], a[i], b[j]);
        }
    };

    load_tiles(0, 0);
    for (int t = 0; t < nt; t++) {
        if (t + 1 < nt) {
            load_tiles(t + 1, (t + 1) & 1);
            asm volatile("cp.async.wait_group 1;");
        } else {
            asm volatile("cp.async.wait_group 0;");
        }
        __syncthreads();
        compute(t & 1);
        __syncthreads();
    }

#pragma unroll
    for (int i = 0; i < 2; i++) {
        int mr = m0 + wm * 32 + i * 16 + gid;
#pragma unroll
        for (int j = 0; j < 8; j++) {
            int col = n0 + wn * 64 + j * 8 + 2 * tg;
            *(float2*)(Cb + (long long)mr * SEQ + col)       = make_float2(c[i][j][0], c[i][j][1]);
            *(float2*)(Cb + (long long)(mr + 8) * SEQ + col) = make_float2(c[i][j][2], c[i][j][3]);
        }
    }
}

// O = P * V per batch (NN), causal K-bound at m0+128. P, V pre-rounded.
__global__ __launch_bounds__(256, 2) void gemm_pv_tc(
    const float* __restrict__ P, const float* __restrict__ V, float* __restrict__ O)
{
    const int m0 = blockIdx.y * 128;
    const int n0 = blockIdx.x * 128;
    const int z  = blockIdx.z;

    const float* Pb = P + (long long)z * SEQ * SEQ + (long long)m0 * SEQ;
    const float* Vb = V + (long long)z * SEQ * DIM;
    float*       Ob = O + (long long)z * SEQ * DIM;

    extern __shared__ float sm[];
    float* Psm = sm;
    float* Vsm = sm + 2 * ATILE;
    const uint32_t pB = (uint32_t)__cvta_generic_to_shared(Psm);
    const uint32_t vB = (uint32_t)__cvta_generic_to_shared(Vsm);

    const int tid  = threadIdx.x;
    const int lane = tid & 31, warp = tid >> 5;
    const int wm = warp >> 1, wn = warp & 1;
    const int gid = lane >> 2, tg = lane & 3;

    float c[2][8][4];
#pragma unroll
    for (int i = 0; i < 2; i++)
#pragma unroll
        for (int j = 0; j < 8; j++)
#pragma unroll
            for (int e = 0; e < 4; e++) c[i][j][e] = 0.f;

    const int nt = (m0 + 128) >> 5;

    auto load_tiles = [&](int t, int buf) {
        const float* Pg = Pb + t * 32;
        const float* Vg = Vb + (long long)(t * 32) * DIM + n0;
#pragma unroll
        for (int i = 0; i < 4; i++) {
            int idx = tid + i * 256;
            int prow = idx >> 3, pkc = (idx & 7) << 2;
            cpasync16(pB + (uint32_t)(buf * ATILE + prow * PADA + pkc) * 4u,
                      Pg + (long long)prow * SEQ + pkc);
            int vrow = idx >> 5, vc = (idx & 31) << 2;
            cpasync16(vB + (uint32_t)(buf * VTILE + vrow * PADV + vc) * 4u,
                      Vg + (long long)vrow * DIM + vc);
        }
        asm volatile("cp.async.commit_group;");
    };

    auto compute = [&](int buf) {
        const float* Pt = Psm + buf * ATILE;
        const float* Vt = Vsm + buf * VTILE;
#pragma unroll
        for (int ks = 0; ks < 4; ks++) {
            const int k0 = ks * 8;
            uint32_t a[2][4];
#pragma unroll
            for (int i = 0; i < 2; i++) {
                int m = wm * 32 + i * 16 + gid;
                a[i][0] = __float_as_uint(Pt[m * PADA + k0 + tg]);
                a[i][1] = __float_as_uint(Pt[(m + 8) * PADA + k0 + tg]);
                a[i][2] = __float_as_uint(Pt[m * PADA + k0 + tg + 4]);
                a[i][3] = __float_as_uint(Pt[(m + 8) * PADA + k0 + tg + 4]);
            }
            uint32_t b[8][2];
#pragma unroll
            for (int j = 0; j < 8; j++) {
                int n = wn * 64 + j * 8 + gid;
                b[j][0] = __float_as_uint(Vt[(k0 + tg) * PADV + n]);
                b[j][1] = __float_as_uint(Vt[(k0 + tg + 4) * PADV + n]);
            }
#pragma unroll
            for (int i = 0; i < 2; i++)
#pragma unroll
                for (int j = 0; j < 8; j++) mma_tf32(c[i][j], a[i], b[j]);
        }
    };

    load_tiles(0, 0);
    for (int t = 0; t < nt; t++) {
        if (t + 1 < nt) {
            load_tiles(t + 1, (t + 1) & 1);
            asm volatile("cp.async.wait_group 1;");
        } else {
            asm volatile("cp.async.wait_group 0;");
        }
        __syncthreads();
        compute(t & 1);
        __syncthreads();
    }

#pragma unroll
    for (int i = 0; i < 2; i++) {
        int mr = m0 + wm * 32 + i * 16 + gid;
#pragma unroll
        for (int j = 0; j < 8; j++) {
            int col = n0 + wn * 64 + j * 8 + 2 * tg;
            *(float2*)(Ob + (long long)mr * DIM + col)       = make_float2(c[i][j][0], c[i][j][1]);
            *(float2*)(Ob + (long long)(mr + 8) * DIM + col) = make_float2(c[i][j][2], c[i][j][3]);
        }
    }
}

// Causal softmax; output rounded to tf32 and zero-padded to 128 boundary.
__global__ __launch_bounds__(256) void softmax_causal(float* __restrict__ S)
{
    const int row = blockIdx.x;
    const int q   = row & (SEQ - 1);
    float* Sr = S + (long long)row * SEQ;

    __shared__ float buf[SEQ];
    __shared__ float red[256];
    const int tid = threadIdx.x;
    const int L   = q + 1;
    const float scale = 0.03125f;   // 1/sqrt(1024)

    float m = -3.402823466e38f;
    for (int j = tid; j < L; j += 256) {
        float v = Sr[j];
        buf[j] = v;
        m = fmaxf(m, v);
    }
    red[tid] = m; __syncthreads();
    for (int s = 128; s; s >>= 1) {
        if (tid < s) red[tid] = fmaxf(red[tid], red[tid + s]);
        __syncthreads();
    }
    const float mv = red[0];
    __syncthreads();

    float sum = 0.f;
    for (int j = tid; j < L; j += 256) {
        float e = __expf((buf[j] - mv) * scale);
        buf[j] = e;
        sum += e;
    }
    red[tid] = sum; __syncthreads();
    for (int s = 128; s; s >>= 1) {
        if (tid < s) red[tid] += red[tid + s];
        __syncthreads();
    }
    const float inv = 1.0f / red[0];

    const int pend = ((q >> 7) + 1) << 7;
    for (int j = tid; j < pend; j += 256)
        Sr[j] = (j < L) ? rnd_tf32(buf[j] * inv) : 0.f;
}

extern "C" void kernel_launch(void* const* d_in, const int* in_sizes, int n_in,
                              void* d_out, int out_size)
{
    const float* x  = (const float*)d_in[0];
    const float* Wq = (const float*)d_in[1];
    const float* Wk = (const float*)d_in[2];
    const float* Wv = (const float*)d_in[3];
    float* out = (float*)d_out;

    float *X, *WQ, *WK, *WV, *Q, *K, *V, *S;
    cudaGetSymbolAddress((void**)&X,  g_X);
    cudaGetSymbolAddress((void**)&WQ, g_Wq);
    cudaGetSymbolAddress((void**)&WK, g_Wk);
    cudaGetSymbolAddress((void**)&WV, g_Wv);
    cudaGetSymbolAddress((void**)&Q,  g_Q);
    cudaGetSymbolAddress((void**)&K,  g_K);
    cudaGetSymbolAddress((void**)&V,  g_V);
    cudaGetSymbolAddress((void**)&S,  g_S);

    const int smemNT = 4 * ATILE * 4;
    const int smemPV = (2 * ATILE + 2 * VTILE) * 4;
    cudaFuncSetAttribute(gemm_qkv_tc, cudaFuncAttributeMaxDynamicSharedMemorySize, smemNT);
    cudaFuncSetAttribute(gemm_qk_tc,  cudaFuncAttributeMaxDynamicSharedMemorySize, smemNT);
    cudaFuncSetAttribute(gemm_pv_tc,  cudaFuncAttributeMaxDynamicSharedMemorySize, smemPV);

    // Pre-round inputs to tf32 (RNA) once.
    const int nx4 = (BATCH * SEQ * DIM) / 4;
    const int nw4 = (DIM * DIM) / 4;
    round_tf32_kernel<<<(nx4 + 255) / 256, 256>>>(x,  X,  nx4);
    round_tf32_kernel<<<(nw4 + 255) / 256, 256>>>(Wq, WQ, nw4);
    round_tf32_kernel<<<(nw4 + 255) / 256, 256>>>(Wk, WK, nw4);
    round_tf32_kernel<<<(nw4 + 255) / 256, 256>>>(Wv, WV, nw4);

    dim3 blk(256);

    // Fused Q/K/V projections (z selects weight/output).
    dim3 g1(DIM / 128, (BATCH * SEQ) / 128, 3);
    gemm_qkv_tc<<<g1, blk, smemNT>>>(X, WQ, WK, WV, Q, K, V);

    dim3 g2(SEQ / 128, SEQ / 128, BATCH);
    gemm_qk_tc<<<g2, blk, smemNT>>>(Q, K, S);

    softmax_causal<<<BATCH * SEQ, 256>>>(S);

    dim3 g3(DIM / 128, SEQ / 128, BATCH);
    gemm_pv_tc<<<g3, blk, smemPV>>>(S, V, out);
}

// round 9
// speedup vs baseline: 4.5092x; 1.1308x over previous
#include <cuda_runtime.h>
#include <cstdint>

// CausalAttention via tf32 mma.sync tensor cores.
// B=4, N=2048, D=1024, fp32 in/out.
// R6 (4th submit; repeated infra timeouts): latency-exposure fixes.
// ldmatrix.x4 fragment loads (6 LDSM/ks vs 24 LDS), 3-stage cp.async pipeline
// with a single __syncthreads per k-tile, shfl-based softmax reductions.
// Numerics identical to R3/R5 (tf32 RNA pre-rounding).

#define BATCH 4
#define SEQ   2048
#define DIM   1024

#define PADA 36              // 128x32 tiles stored [r][36]
#define PADV 136             // 32x128 V tiles stored [k][136]
#define ATILE (128 * PADA)   // 4608 floats / 18432 B
#define VTILE (32 * PADV)    // 4352 floats / 17408 B
#define STAGES 3

__device__ float g_X [BATCH * SEQ * DIM];
__device__ float g_Wq[DIM * DIM];
__device__ float g_Wk[DIM * DIM];
__device__ float g_Wv[DIM * DIM];
__device__ float g_Q [BATCH * SEQ * DIM];
__device__ float g_K [BATCH * SEQ * DIM];
__device__ float g_V [BATCH * SEQ * DIM];
__device__ float g_S [BATCH * SEQ * SEQ];

__device__ __forceinline__ uint32_t f2tf32(float f) {
    uint32_t u;
    asm("cvt.rna.tf32.f32 %0, %1;" : "=r"(u) : "f"(f));
    return u;
}
__device__ __forceinline__ float rnd_tf32(float f) {
    return __uint_as_float(f2tf32(f));
}

__device__ __forceinline__ void cpasync16(uint32_t dst, const void* src) {
    asm volatile("cp.async.cg.shared.global [%0], [%1], 16;" :: "r"(dst), "l"(src));
}

__device__ __forceinline__ void ldsm_x4(uint32_t& r0, uint32_t& r1,
                                        uint32_t& r2, uint32_t& r3, uint32_t addr) {
    asm volatile("ldmatrix.sync.aligned.m8n8.x4.shared.b16 {%0,%1,%2,%3}, [%4];"
        : "=r"(r0), "=r"(r1), "=r"(r2), "=r"(r3) : "r"(addr));
}

__device__ __forceinline__ void mma_tf32(float c[4], const uint32_t a[4], const uint32_t b[2]) {
    asm volatile(
        "mma.sync.aligned.m16n8k8.row.col.f32.tf32.tf32.f32 "
        "{%0,%1,%2,%3}, {%4,%5,%6,%7}, {%8,%9}, {%0,%1,%2,%3};"
        : "+f"(c[0]), "+f"(c[1]), "+f"(c[2]), "+f"(c[3])
        : "r"(a[0]), "r"(a[1]), "r"(a[2]), "r"(a[3]), "r"(b[0]), "r"(b[1]));
}

__global__ void round_tf32_kernel(const float* __restrict__ src,
                                  float* __restrict__ dst, int n4)
{
    int i = blockIdx.x * blockDim.x + threadIdx.x;
    if (i < n4) {
        float4 v = ((const float4*)src)[i];
        v.x = rnd_tf32(v.x); v.y = rnd_tf32(v.y);
        v.z = rnd_tf32(v.z); v.w = rnd_tf32(v.w);
        ((float4*)dst)[i] = v;
    }
}

// ---------------------------------------------------------------------------
// NT mainloop body (A[M,K] * B[N,K]^T), 128x128 tile, 8 warps, tf32 mma.
// ---------------------------------------------------------------------------
#define NT_MAINLOOP(LDK)                                                        \
    extern __shared__ float sm[];                                               \
    const uint32_t smB = (uint32_t)__cvta_generic_to_shared(sm);                \
    const uint32_t aRegion = smB;                                               \
    const uint32_t bRegion = smB + STAGES * ATILE * 4u;                         \
    const int tid  = threadIdx.x;                                               \
    const int lane = tid & 31, warp = tid >> 5;                                 \
    const int wm = warp >> 1, wn = warp & 1;                                    \
    const int gid = lane >> 2, tg = lane & 3;                                   \
    (void)gid; (void)tg;                                                        \
    const int tile = lane >> 3, trow = lane & 7;                                \
    const uint32_t aLane = (uint32_t)(((wm * 32 + (tile & 1) * 8 + trow) * PADA \
                                       + (tile >> 1) * 4) * 4);                 \
    const int jj = (lane >> 4) & 1, bhalf = (lane >> 3) & 1, brow = lane & 7;   \
    const uint32_t bLane = (uint32_t)(((wn * 64 + jj * 8 + brow) * PADA         \
                                       + bhalf * 4) * 4);                       \
    float c[2][8][4];                                                           \
    _Pragma("unroll")                                                           \
    for (int i = 0; i < 2; i++)                                                 \
        _Pragma("unroll")                                                       \
        for (int j = 0; j < 8; j++)                                             \
            _Pragma("unroll")                                                   \
            for (int e = 0; e < 4; e++) c[i][j][e] = 0.f;                       \
    auto load_tiles = [&](int t, int stage) {                                   \
        const float* Ag = Ab + t * 32;                                          \
        const float* Bg = Bb + t * 32;                                          \
        uint32_t so = (uint32_t)(stage * ATILE) * 4u;                           \
        _Pragma("unroll")                                                       \
        for (int i = 0; i < 4; i++) {                                           \
            int idx = tid + i * 256;                                            \
            int row = idx >> 3, kc = (idx & 7) << 2;                            \
            uint32_t off = so + (uint32_t)(row * PADA + kc) * 4u;               \
            cpasync16(aRegion + off, Ag + (long long)row * (LDK) + kc);         \
            cpasync16(bRegion + off, Bg + (long long)row * (LDK) + kc);         \
        }                                                                       \
        asm volatile("cp.async.commit_group;");                                 \
    };                                                                          \
    auto compute = [&](int stage) {                                             \
        uint32_t sOf = (uint32_t)(stage * ATILE) * 4u;                          \
        uint32_t aS = aRegion + sOf + aLane;                                    \
        uint32_t bS = bRegion + sOf + bLane;                                    \
        _Pragma("unroll")                                                       \
        for (int ks = 0; ks < 4; ks++) {                                        \
            const uint32_t k0b = (uint32_t)(ks * 8) * 4u;                       \
            uint32_t a[2][4];                                                   \
            ldsm_x4(a[0][0], a[0][1], a[0][2], a[0][3], aS + k0b);              \
            ldsm_x4(a[1][0], a[1][1], a[1][2], a[1][3],                         \
                    aS + k0b + 16u * PADA * 4u);                                \
            uint32_t b[8][2];                                                   \
            _Pragma("unroll")                                                   \
            for (int p = 0; p < 4; p++)                                         \
                ldsm_x4(b[2*p][0], b[2*p][1], b[2*p+1][0], b[2*p+1][1],         \
                        bS + k0b + (uint32_t)(p * 16 * PADA) * 4u);             \
            _Pragma("unroll")                                                   \
            for (int i = 0; i < 2; i++)                                         \
                _Pragma("unroll")                                               \
                for (int j = 0; j < 8; j++) mma_tf32(c[i][j], a[i], b[j]);      \
        }                                                                       \
    };                                                                          \
    load_tiles(0, 0);                                                           \
    load_tiles(1, 1);                                                           \
    for (int t = 0; t < nt; t++) {                                              \
        if (t + 1 < nt) { asm volatile("cp.async.wait_group 1;"); }             \
        else            { asm volatile("cp.async.wait_group 0;"); }             \
        __syncthreads();                                                        \
        if (t + 2 < nt) load_tiles(t + 2, (t + 2) % STAGES);                    \
        compute(t % STAGES);                                                    \
    }

// Fused QKV projection: C_z[M,N] = X[M,K] * W_z[N,K]^T, z = 0,1,2. tf32 output.
__global__ __launch_bounds__(256, 2) void gemm_qkv_tc(
    const float* __restrict__ X,
    const float* __restrict__ Wq, const float* __restrict__ Wk,
    const float* __restrict__ Wv,
    float* __restrict__ Q, float* __restrict__ K, float* __restrict__ V)
{
    const int m0 = blockIdx.y * 128;
    const int n0 = blockIdx.x * 128;
    const float* Bw = (blockIdx.z == 0) ? Wq : (blockIdx.z == 1) ? Wk : Wv;
    float*       C  = (blockIdx.z == 0) ? Q  : (blockIdx.z == 1) ? K  : V;
    const float* Ab = X  + (long long)m0 * DIM;
    const float* Bb = Bw + (long long)n0 * DIM;
    const int nt = DIM >> 5;

    NT_MAINLOOP(DIM)

#pragma unroll
    for (int i = 0; i < 2; i++) {
        int mr = m0 + wm * 32 + i * 16 + gid;
#pragma unroll
        for (int j = 0; j < 8; j++) {
            int col = n0 + wn * 64 + j * 8 + 2 * tg;
            *(float2*)(C + (long long)mr * DIM + col) =
                make_float2(rnd_tf32(c[i][j][0]), rnd_tf32(c[i][j][1]));
            *(float2*)(C + (long long)(mr + 8) * DIM + col) =
                make_float2(rnd_tf32(c[i][j][2]), rnd_tf32(c[i][j][3]));
        }
    }
}

// S = Q * K^T per batch (NT), lower-triangular tiles only. Raw fp32 output.
__global__ __launch_bounds__(256, 2) void gemm_qk_tc(
    const float* __restrict__ Q, const float* __restrict__ K,
    float* __restrict__ S)
{
    const int m0 = blockIdx.y * 128;
    const int n0 = blockIdx.x * 128;
    if (n0 > m0) return;
    const int z = blockIdx.z;
    const float* Ab = Q + (long long)z * SEQ * DIM + (long long)m0 * DIM;
    const float* Bb = K + (long long)z * SEQ * DIM + (long long)n0 * DIM;
    float*       Cb = S + (long long)z * SEQ * SEQ;
    const int nt = DIM >> 5;

    NT_MAINLOOP(DIM)

#pragma unroll
    for (int i = 0; i < 2; i++) {
        int mr = m0 + wm * 32 + i * 16 + gid;
#pragma unroll
        for (int j = 0; j < 8; j++) {
            int col = n0 + wn * 64 + j * 8 + 2 * tg;
            *(float2*)(Cb + (long long)mr * SEQ + col)       = make_float2(c[i][j][0], c[i][j][1]);
            *(float2*)(Cb + (long long)(mr + 8) * SEQ + col) = make_float2(c[i][j][2], c[i][j][3]);
        }
    }
}

// O = P * V per batch (NN), causal K-bound at m0+128. ldsm for P, scalar V.
__global__ __launch_bounds__(256, 2) void gemm_pv_tc(
    const float* __restrict__ P, const float* __restrict__ V, float* __restrict__ O)
{
    const int m0 = blockIdx.y * 128;
    const int n0 = blockIdx.x * 128;
    const int z  = blockIdx.z;

    const float* Pb = P + (long long)z * SEQ * SEQ + (long long)m0 * SEQ;
    const float* Vb = V + (long long)z * SEQ * DIM;
    float*       Ob = O + (long long)z * SEQ * DIM;

    extern __shared__ float sm[];
    const uint32_t smB = (uint32_t)__cvta_generic_to_shared(sm);
    const uint32_t pRegion = smB;
    const uint32_t vRegion = smB + STAGES * ATILE * 4u;
    float* Vsm = sm + STAGES * ATILE;

    const int tid  = threadIdx.x;
    const int lane = tid & 31, warp = tid >> 5;
    const int wm = warp >> 1, wn = warp & 1;
    const int gid = lane >> 2, tg = lane & 3;
    const int tile = lane >> 3, trow = lane & 7;
    const uint32_t aLane = (uint32_t)(((wm * 32 + (tile & 1) * 8 + trow) * PADA
                                       + (tile >> 1) * 4) * 4);

    float c[2][8][4];
#pragma unroll
    for (int i = 0; i < 2; i++)
#pragma unroll
        for (int j = 0; j < 8; j++)
#pragma unroll
            for (int e = 0; e < 4; e++) c[i][j][e] = 0.f;

    const int nt = (m0 + 128) >> 5;

    auto load_tiles = [&](int t, int stage) {
        const float* Pg = Pb + t * 32;
        const float* Vg = Vb + (long long)(t * 32) * DIM + n0;
        uint32_t soP = (uint32_t)(stage * ATILE) * 4u;
        uint32_t soV = (uint32_t)(stage * VTILE) * 4u;
#pragma unroll
        for (int i = 0; i < 4; i++) {
            int idx = tid + i * 256;
            int prow = idx >> 3, pkc = (idx & 7) << 2;
            cpasync16(pRegion + soP + (uint32_t)(prow * PADA + pkc) * 4u,
                      Pg + (long long)prow * SEQ + pkc);
            int vrow = idx >> 5, vc = (idx & 31) << 2;
            cpasync16(vRegion + soV + (uint32_t)(vrow * PADV + vc) * 4u,
                      Vg + (long long)vrow * DIM + vc);
        }
        asm volatile("cp.async.commit_group;");
    };

    auto compute = [&](int stage) {
        uint32_t aS = pRegion + (uint32_t)(stage * ATILE) * 4u + aLane;
        const float* Vt = Vsm + stage * VTILE;
#pragma unroll
        for (int ks = 0; ks < 4; ks++) {
            const int k0 = ks * 8;
            uint32_t a[2][4];
            ldsm_x4(a[0][0], a[0][1], a[0][2], a[0][3], aS + (uint32_t)(k0 * 4));
            ldsm_x4(a[1][0], a[1][1], a[1][2], a[1][3],
                    aS + (uint32_t)(k0 * 4) + 16u * PADA * 4u);
            uint32_t b[8][2];
#pragma unroll
            for (int j = 0; j < 8; j++) {
                int n = wn * 64 + j * 8 + gid;
                b[j][0] = __float_as_uint(Vt[(k0 + tg) * PADV + n]);
                b[j][1] = __float_as_uint(Vt[(k0 + tg + 4) * PADV + n]);
            }
#pragma unroll
            for (int i = 0; i < 2; i++)
#pragma unroll
                for (int j = 0; j < 8; j++) mma_tf32(c[i][j], a[i], b[j]);
        }
    };

    load_tiles(0, 0);
    load_tiles(1, 1);
    for (int t = 0; t < nt; t++) {
        if (t + 1 < nt) { asm volatile("cp.async.wait_group 1;"); }
        else            { asm volatile("cp.async.wait_group 0;"); }
        __syncthreads();
        if (t + 2 < nt) load_tiles(t + 2, (t + 2) % STAGES);
        compute(t % STAGES);
    }

#pragma unroll
    for (int i = 0; i < 2; i++) {
        int mr = m0 + wm * 32 + i * 16 + gid;
#pragma unroll
        for (int j = 0; j < 8; j++) {
            int col = n0 + wn * 64 + j * 8 + 2 * tg;
            *(float2*)(Ob + (long long)mr * DIM + col)       = make_float2(c[i][j][0], c[i][j][1]);
            *(float2*)(Ob + (long long)(mr + 8) * DIM + col) = make_float2(c[i][j][2], c[i][j][3]);
        }
    }
}

// Causal softmax; shfl-based reductions; output tf32-rounded + zero-padded.
__global__ __launch_bounds__(256) void softmax_causal(float* __restrict__ S)
{
    const int row = blockIdx.x;
    const int q   = row & (SEQ - 1);
    float* Sr = S + (long long)row * SEQ;

    __shared__ float buf[SEQ];
    __shared__ float wred[8];
    const int tid = threadIdx.x;
    const int lane = tid & 31, wid = tid >> 5;
    const int L   = q + 1;
    const float scale = 0.03125f;   // 1/sqrt(1024)

    float m = -3.402823466e38f;
    for (int j = tid; j < L; j += 256) {
        float v = Sr[j];
        buf[j] = v;
        m = fmaxf(m, v);
    }
#pragma unroll
    for (int o = 16; o; o >>= 1) m = fmaxf(m, __shfl_xor_sync(0xffffffffu, m, o));
    if (lane == 0) wred[wid] = m;
    __syncthreads();
    float mv = wred[0];
#pragma unroll
    for (int i = 1; i < 8; i++) mv = fmaxf(mv, wred[i]);
    __syncthreads();

    float sum = 0.f;
    for (int j = tid; j < L; j += 256) {
        float e = __expf((buf[j] - mv) * scale);
        buf[j] = e;
        sum += e;
    }
#pragma unroll
    for (int o = 16; o; o >>= 1) sum += __shfl_xor_sync(0xffffffffu, sum, o);
    if (lane == 0) wred[wid] = sum;
    __syncthreads();
    float tot = wred[0];
#pragma unroll
    for (int i = 1; i < 8; i++) tot += wred[i];
    const float inv = 1.0f / tot;

    const int pend = ((q >> 7) + 1) << 7;
    for (int j = tid; j < pend; j += 256)
        Sr[j] = (j < L) ? rnd_tf32(buf[j] * inv) : 0.f;
}

extern "C" void kernel_launch(void* const* d_in, const int* in_sizes, int n_in,
                              void* d_out, int out_size)
{
    const float* x  = (const float*)d_in[0];
    const float* Wq = (const float*)d_in[1];
    const float* Wk = (const float*)d_in[2];
    const float* Wv = (const float*)d_in[3];
    float* out = (float*)d_out;

    float *X, *WQ, *WK, *WV, *Q, *K, *V, *S;
    cudaGetSymbolAddress((void**)&X,  g_X);
    cudaGetSymbolAddress((void**)&WQ, g_Wq);
    cudaGetSymbolAddress((void**)&WK, g_Wk);
    cudaGetSymbolAddress((void**)&WV, g_Wv);
    cudaGetSymbolAddress((void**)&Q,  g_Q);
    cudaGetSymbolAddress((void**)&K,  g_K);
    cudaGetSymbolAddress((void**)&V,  g_V);
    cudaGetSymbolAddress((void**)&S,  g_S);

    const int smemNT = STAGES * 2 * ATILE * 4;              // 110592 B
    const int smemPV = STAGES * (ATILE + VTILE) * 4;        // 107520 B
    cudaFuncSetAttribute(gemm_qkv_tc, cudaFuncAttributeMaxDynamicSharedMemorySize, smemNT);
    cudaFuncSetAttribute(gemm_qk_tc,  cudaFuncAttributeMaxDynamicSharedMemorySize, smemNT);
    cudaFuncSetAttribute(gemm_pv_tc,  cudaFuncAttributeMaxDynamicSharedMemorySize, smemPV);

    // Pre-round inputs to tf32 (RNA) once.
    const int nx4 = (BATCH * SEQ * DIM) / 4;
    const int nw4 = (DIM * DIM) / 4;
    round_tf32_kernel<<<(nx4 + 255) / 256, 256>>>(x,  X,  nx4);
    round_tf32_kernel<<<(nw4 + 255) / 256, 256>>>(Wq, WQ, nw4);
    round_tf32_kernel<<<(nw4 + 255) / 256, 256>>>(Wk, WK, nw4);
    round_tf32_kernel<<<(nw4 + 255) / 256, 256>>>(Wv, WV, nw4);

    dim3 blk(256);

    dim3 g1(DIM / 128, (BATCH * SEQ) / 128, 3);
    gemm_qkv_tc<<<g1, blk, smemNT>>>(X, WQ, WK, WV, Q, K, V);

    dim3 g2(SEQ / 128, SEQ / 128, BATCH);
    gemm_qk_tc<<<g2, blk, smemNT>>>(Q, K, S);

    softmax_causal<<<BATCH * SEQ, 256>>>(S);

    dim3 g3(DIM / 128, SEQ / 128, BATCH);
    gemm_pv_tc<<<g3, blk, smemPV>>>(S, V, out);
}